// round 1
// baseline (speedup 1.0000x reference)
#include <cuda_runtime.h>
#include <math.h>

#define N_ROWS 8192
#define FD 128
#define FD4 (FD/4)
#define INV_T (1.0f/0.07f)
#define ROWS_PER_CTA 64
#define TILE_C 128
#define NUM_CTAS (N_ROWS / ROWS_PER_CTA)   // 128
#define NUM_TILES (N_ROWS / TILE_C)        // 64
#define NBATCH 512
#define NCLASS 16

// ---------------- device-global scratch (no allocations allowed) ----------------
__device__ float  g_F[NCLASS * FD];    // per-class feature sums (batch-level, x16 rows each)
__device__ int    g_cnt[NCLASS];       // batches per class
__device__ float  g_Bb[NBATCH * FD];   // per-batch (16-row) feature sums
__device__ float  g_m[N_ROWS];         // per-row masked max (dot units)
__device__ float  g_l[N_ROWS];         // per-row masked sumexp (logit units, shifted by m)
__device__ double g_noise;             // sum of same-group off-diag dots
__device__ double g_class;             // sum of per-row class-loss terms

// ---------------- kernel 0: zero accumulators ----------------
__global__ void zero_kernel() {
    int t = threadIdx.x;
    for (int i = t; i < NCLASS * FD; i += blockDim.x) g_F[i] = 0.f;
    if (t < NCLASS) g_cnt[t] = 0;
    if (t == 0) { g_noise = 0.0; g_class = 0.0; }
}

// ---------------- kernel 1: per-batch sums, class sums, noise closed form ----------------
// grid = 512 (one per batch of 16 rows), block = 128 (one thread per feature dim)
__global__ void precompute_kernel(const float* __restrict__ f,
                                  const int* __restrict__ labels) {
    int b = blockIdx.x;
    int t = threadIdx.x;
    float s16 = 0.f, s8a = 0.f, s8b = 0.f, ssq = 0.f;
#pragma unroll
    for (int r = 0; r < 16; r++) {
        float v = f[(b * 16 + r) * FD + t];
        s16 += v;
        if (r < 8) s8a += v; else s8b += v;
        ssq += v * v;
    }
    g_Bb[b * FD + t] = s16;
    int lab = labels[b];
    atomicAdd(&g_F[lab * FD + t], s16);
    if (t == 0) atomicAdd(&g_cnt[lab], 1);

    // noise term per-dim: |G0|^2 + |G1|^2 - sum |f_i|^2  (groups = 8-row halves)
    float c = s8a * s8a + s8b * s8b - ssq;
#pragma unroll
    for (int sh = 16; sh > 0; sh >>= 1)
        c += __shfl_xor_sync(0xffffffffu, c, sh);
    __shared__ float red[4];
    if ((t & 31) == 0) red[t >> 5] = c;
    __syncthreads();
    if (t == 0) {
        float tot = red[0] + red[1] + red[2] + red[3];
        atomicAdd(&g_noise, (double)tot);
    }
}

// ---------------- kernel 2: masked per-row max + logsumexp over the gram matrix ----------------
// 128 CTAs x 64 rows. Tiled fp32 GEMM (64x128 tile, 8x8 microtile), online softmax epilogue.
__global__ void __launch_bounds__(128)
gram_lse_kernel(const float* __restrict__ f) {
    extern __shared__ float smem[];
    float* As = smem;                       // [FD][ROWS_PER_CTA] k-major
    float* Bs = smem + FD * ROWS_PER_CTA;   // [FD][TILE_C]       k-major

    int tid = threadIdx.x;
    int tx = tid & 15;    // column group (16 x 8 cols = 128)
    int ty = tid >> 4;    // row group    (8  x 8 rows = 64)
    int row0 = blockIdx.x * ROWS_PER_CTA;

    const float4* f4 = (const float4*)f;

    // Load A tile (64 rows x 128 k), transposed to k-major. Conflict-free STS.
    for (int i = tid; i < ROWS_PER_CTA * FD4; i += 128) {
        int r = i & (ROWS_PER_CTA - 1);
        int q = i >> 6;
        float4 v = f4[(row0 + r) * FD4 + q];
        As[(4 * q + 0) * ROWS_PER_CTA + r] = v.x;
        As[(4 * q + 1) * ROWS_PER_CTA + r] = v.y;
        As[(4 * q + 2) * ROWS_PER_CTA + r] = v.z;
        As[(4 * q + 3) * ROWS_PER_CTA + r] = v.w;
    }

    int rbid[8];
#pragma unroll
    for (int r = 0; r < 8; r++) rbid[r] = (row0 + ty * 8 + r) >> 4;

    float m_run[8], l_run[8];
#pragma unroll
    for (int r = 0; r < 8; r++) { m_run[r] = -3.0e38f; l_run[r] = 0.f; }

    for (int tile = 0; tile < NUM_TILES; tile++) {
        int c0 = tile * TILE_C;
        __syncthreads();
        // Load B tile (128 cols x 128 k), transposed to k-major.
        for (int i = tid; i < TILE_C * FD4; i += 128) {
            int r = i & (TILE_C - 1);
            int q = i >> 7;
            float4 v = f4[(c0 + r) * FD4 + q];
            Bs[(4 * q + 0) * TILE_C + r] = v.x;
            Bs[(4 * q + 1) * TILE_C + r] = v.y;
            Bs[(4 * q + 2) * TILE_C + r] = v.z;
            Bs[(4 * q + 3) * TILE_C + r] = v.w;
        }
        __syncthreads();

        float acc[8][8];
#pragma unroll
        for (int r = 0; r < 8; r++)
#pragma unroll
            for (int j = 0; j < 8; j++) acc[r][j] = 0.f;

#pragma unroll 4
        for (int k = 0; k < FD; k++) {
            float4 a0 = *(const float4*)&As[k * ROWS_PER_CTA + ty * 8];
            float4 a1 = *(const float4*)&As[k * ROWS_PER_CTA + ty * 8 + 4];
            float4 b0 = *(const float4*)&Bs[k * TILE_C + tx * 8];
            float4 b1 = *(const float4*)&Bs[k * TILE_C + tx * 8 + 4];
            float av[8] = {a0.x, a0.y, a0.z, a0.w, a1.x, a1.y, a1.z, a1.w};
            float bv[8] = {b0.x, b0.y, b0.z, b0.w, b1.x, b1.y, b1.z, b1.w};
#pragma unroll
            for (int r = 0; r < 8; r++)
#pragma unroll
                for (int j = 0; j < 8; j++)
                    acc[r][j] = fmaf(av[r], bv[j], acc[r][j]);
        }

        // Epilogue: masked online max / sumexp. Mask = same-batch (16-col blocks).
        int cb[8];
#pragma unroll
        for (int j = 0; j < 8; j++) cb[j] = (c0 + tx * 8 + j) >> 4;

#pragma unroll
        for (int r = 0; r < 8; r++) {
            float vmax = -3.0e38f;
#pragma unroll
            for (int j = 0; j < 8; j++) {
                float x = (rbid[r] != cb[j]) ? acc[r][j] : -3.0e38f;
                acc[r][j] = x;
                vmax = fmaxf(vmax, x);
            }
#pragma unroll
            for (int sh = 1; sh < 16; sh <<= 1)
                vmax = fmaxf(vmax, __shfl_xor_sync(0xffffffffu, vmax, sh));
            float newM = fmaxf(m_run[r], vmax);
            float s = 0.f;
            // skip entire 128-col row-tile if it cannot contribute (exp underflow)
            if ((vmax - newM) * INV_T > -87.f) {
#pragma unroll
                for (int j = 0; j < 8; j++) {
                    float t = (acc[r][j] - newM) * INV_T;
                    if (t > -87.f) s += __expf(t);
                }
            }
#pragma unroll
            for (int sh = 1; sh < 16; sh <<= 1)
                s += __shfl_xor_sync(0xffffffffu, s, sh);
            float sc = __expf((m_run[r] - newM) * INV_T);  // 0 on first tile (-inf arg)
            l_run[r] = l_run[r] * sc + s;
            m_run[r] = newM;
        }
    }

    if (tx == 0) {
#pragma unroll
        for (int r = 0; r < 8; r++) {
            g_m[row0 + ty * 8 + r] = m_run[r];
            g_l[row0 + ty * 8 + r] = l_run[r];
        }
    }
}

// ---------------- kernel 3: per-row class loss term via closed-form positive sums ----------------
// 512 warps, 16 rows each (one batch per warp).
__global__ void finish_kernel(const float* __restrict__ f,
                              const int* __restrict__ labels) {
    int w = (blockIdx.x * blockDim.x + threadIdx.x) >> 5;
    int lane = threadIdx.x & 31;
    float wsum = 0.f;
    for (int r = 0; r < 16; r++) {
        int i = w * 16 + r;
        int b = i >> 4;
        int lab = labels[b];
        float d = 0.f;
#pragma unroll
        for (int q = 0; q < 4; q++) {
            int t = lane + 32 * q;
            d += f[i * FD + t] * (g_F[lab * FD + t] - g_Bb[b * FD + t]);
        }
#pragma unroll
        for (int sh = 16; sh > 0; sh >>= 1)
            d += __shfl_xor_sync(0xffffffffu, d, sh);
        if (lane == 0) {
            float P = (float)(g_cnt[lab] * 16 - 16);
            float lse = g_m[i] * INV_T + logf(g_l[i]);
            float term = 0.f;
            if (P > 0.f) term = -(d * INV_T - P * lse) / (P + 1e-8f);
            wsum += term;
        }
    }
    if (lane == 0) atomicAdd(&g_class, (double)wsum);
}

// ---------------- kernel 4: final scalar ----------------
__global__ void final_kernel(float* __restrict__ out) {
    double loss_class = g_class / (double)N_ROWS;
    double s_noise_logits = g_noise * (double)INV_T;
    double loss_noise = -(s_noise_logits / ((double)N_ROWS * 7.0)) / 0.07;
    double a = 1.0 / 3.0;
    double loss = a * loss_class + a * loss_noise;
    loss = loss * (0.07 / 0.07);  // TEMP / BASE_TEMP
    out[0] = (float)loss;
}

// ---------------- launch ----------------
extern "C" void kernel_launch(void* const* d_in, const int* in_sizes, int n_in,
                              void* d_out, int out_size) {
    const float* f = (const float*)d_in[0];
    const int* labels = (const int*)d_in[1];
    float* out = (float*)d_out;

    const int smem_bytes = (FD * ROWS_PER_CTA + FD * TILE_C) * (int)sizeof(float); // 96 KB
    cudaFuncSetAttribute(gram_lse_kernel,
                         cudaFuncAttributeMaxDynamicSharedMemorySize, smem_bytes);

    zero_kernel<<<1, 256>>>();
    precompute_kernel<<<NBATCH, 128>>>(f, labels);
    gram_lse_kernel<<<NUM_CTAS, 128, smem_bytes>>>(f);
    finish_kernel<<<64, 256>>>(f, labels);
    final_kernel<<<1, 1>>>(out);
}

// round 3
// speedup vs baseline: 3.5870x; 3.5870x over previous
#include <cuda_runtime.h>
#include <cuda_bf16.h>
#include <math.h>
#include <stdint.h>

#define N_ROWS 8192
#define FD 128
#define INV_T 14.2857142857142857f   // 1/0.07
#define NBATCH 512
#define NCLASS 16
#define NT 32              // column tiles per CTA (4096/128)

// ---------------- device-global scratch ----------------
// pre-swizzled bf16 hi/lo, 16B chunks: [rowblock(64)][r(128)][chunk(16)]
__device__ uint4  g_fhi_sw[N_ROWS * 16];
__device__ uint4  g_flo_sw[N_ROWS * 16];
__device__ float  g_F[NCLASS * FD];
__device__ int    g_cnt[NCLASS];
__device__ float  g_Bb[NBATCH * FD];
__device__ float  g_mp[2 * N_ROWS];
__device__ float  g_lp[2 * N_ROWS];
__device__ double g_noise;
__device__ double g_class;

// ---------------- helpers ----------------
__device__ __forceinline__ uint32_t smem_u32(const void* p) {
    uint32_t a;
    asm("{ .reg .u64 t; cvta.to.shared.u64 t, %1; cvt.u32.u64 %0, t; }" : "=r"(a) : "l"(p));
    return a;
}
__device__ __forceinline__ void cp16(uint32_t s, const void* g) {
    asm volatile("cp.async.cg.shared.global [%0], [%1], 16;" :: "r"(s), "l"(g) : "memory");
}
#define CP_COMMIT() asm volatile("cp.async.commit_group;" ::: "memory")
#define CP_WAIT1()  asm volatile("cp.async.wait_group 1;" ::: "memory")
#define CP_WAIT0()  asm volatile("cp.async.wait_group 0;" ::: "memory")

#define LDSM4(R, addr) \
    asm volatile("ldmatrix.sync.aligned.m8n8.x4.shared.b16 {%0,%1,%2,%3}, [%4];" \
        : "=r"((R)[0]), "=r"((R)[1]), "=r"((R)[2]), "=r"((R)[3]) : "r"(addr))

#define MMA(C, A, B0, B1) \
    asm volatile("mma.sync.aligned.m16n8k16.row.col.f32.bf16.bf16.f32 " \
        "{%0,%1,%2,%3}, {%4,%5,%6,%7}, {%8,%9}, {%0,%1,%2,%3};" \
        : "+f"((C)[0]), "+f"((C)[1]), "+f"((C)[2]), "+f"((C)[3]) \
        : "r"((A)[0]), "r"((A)[1]), "r"((A)[2]), "r"((A)[3]), "r"(B0), "r"(B1))

__device__ __forceinline__ uint32_t pack_bf2(__nv_bfloat16 a, __nv_bfloat16 b) {
    __nv_bfloat162 t(a, b);
    return *reinterpret_cast<uint32_t*>(&t);
}

// ---------------- kernel 0: zero accumulators ----------------
__global__ void zero_kernel() {
    int t = threadIdx.x;
    for (int i = t; i < NCLASS * FD; i += blockDim.x) g_F[i] = 0.f;
    if (t < NCLASS) g_cnt[t] = 0;
    if (t == 0) { g_noise = 0.0; g_class = 0.0; }
}

// ---------------- kernel 1: fp32 -> swizzled bf16 hi/lo ----------------
// one thread = one 16B chunk (8 elements). grid 512 x 256.
__global__ void prep_kernel(const float* __restrict__ f) {
    int idx = blockIdx.x * 256 + threadIdx.x;   // 0..131071
    int row = idx >> 4;
    int c = idx & 15;
    float4 v0 = ((const float4*)f)[row * 32 + c * 2];
    float4 v1 = ((const float4*)f)[row * 32 + c * 2 + 1];
    float vs[8] = { v0.x, v0.y, v0.z, v0.w, v1.x, v1.y, v1.z, v1.w };
    uint32_t hi[4], lo[4];
#pragma unroll
    for (int k = 0; k < 4; k++) {
        float a = vs[2 * k], b = vs[2 * k + 1];
        __nv_bfloat16 ha = __float2bfloat16(a), hb = __float2bfloat16(b);
        __nv_bfloat16 la = __float2bfloat16(a - __bfloat162float(ha));
        __nv_bfloat16 lb = __float2bfloat16(b - __bfloat162float(hb));
        hi[k] = pack_bf2(ha, hb);
        lo[k] = pack_bf2(la, lb);
    }
    int dst = ((row >> 7) << 11) + ((row & 127) << 4) + (c ^ (row & 7));
    g_fhi_sw[dst] = make_uint4(hi[0], hi[1], hi[2], hi[3]);
    g_flo_sw[dst] = make_uint4(lo[0], lo[1], lo[2], lo[3]);
}

// ---------------- kernel 2: per-batch sums, class sums, noise closed form ----------------
__global__ void precompute_kernel(const float* __restrict__ f,
                                  const int* __restrict__ labels) {
    int b = blockIdx.x;
    int t = threadIdx.x;
    float s16 = 0.f, s8a = 0.f, s8b = 0.f, ssq = 0.f;
#pragma unroll
    for (int r = 0; r < 16; r++) {
        float v = f[(b * 16 + r) * FD + t];
        s16 += v;
        if (r < 8) s8a += v; else s8b += v;
        ssq += v * v;
    }
    g_Bb[b * FD + t] = s16;
    int lab = labels[b];
    atomicAdd(&g_F[lab * FD + t], s16);
    if (t == 0) atomicAdd(&g_cnt[lab], 1);
    float c = s8a * s8a + s8b * s8b - ssq;
#pragma unroll
    for (int sh = 16; sh > 0; sh >>= 1)
        c += __shfl_xor_sync(0xffffffffu, c, sh);
    __shared__ float red[4];
    if ((t & 31) == 0) red[t >> 5] = c;
    __syncthreads();
    if (t == 0) atomicAdd(&g_noise, (double)(red[0] + red[1] + red[2] + red[3]));
}

// ---------------- kernel 3: HMMA gram + masked online logsumexp ----------------
// grid 128 (64 rowblocks x 2 halves), 512 threads = 16 warps (4x4).
#define SM_A_HI 0
#define SM_A_LO 32768
#define SM_BB(buf, hl) (65536 + (buf) * 65536 + (hl) * 32768)

__global__ void __launch_bounds__(512, 1) gram_kernel() {
    extern __shared__ char smraw[];
    uint32_t su = smem_u32(smraw);
    uint32_t base = (su + 1023u) & ~1023u;
    char* cbase_ptr = smraw + (base - su);

    int tid = threadIdx.x;
    int l = tid & 31;
    int wid = tid >> 5;
    int wx = wid & 3, wy = wid >> 2;
    int rb = blockIdx.x >> 1, half = blockIdx.x & 1;
    int row0 = rb * 128;
    int colbase = half * 4096;
    int mb = wy * 32, nb = wx * 32;

    // ---- prologue: A tiles + B tile 0 (group 0) ----
    {
        const uint4* sAh = g_fhi_sw + rb * 2048;
        const uint4* sAl = g_flo_sw + rb * 2048;
        int blk0 = half * 32;
        const uint4* sBh = g_fhi_sw + blk0 * 2048;
        const uint4* sBl = g_flo_sw + blk0 * 2048;
#pragma unroll
        for (int i = 0; i < 4; i++) {
            int ch = tid * 4 + i;
            cp16(base + SM_A_HI + ch * 16, sAh + ch);
            cp16(base + SM_A_LO + ch * 16, sAl + ch);
            cp16(base + SM_BB(0, 0) + ch * 16, sBh + ch);
            cp16(base + SM_BB(0, 1) + ch * 16, sBl + ch);
        }
        CP_COMMIT();
    }

    // ---- lane addressing ----
    int rowA = l & 15;
    int cA = l >> 4;           // 0/1
    int xA = rowA & 7;
    int rowB = (l & 7) + ((l >> 4) << 3);
    int cB = (l >> 3) & 1;
    int xB = rowB & 7;
    uint32_t aHi = base + SM_A_HI + (mb + rowA) * 256;
    uint32_t aLo = base + SM_A_LO + (mb + rowA) * 256;

    float m[4], lv[4];
#pragma unroll
    for (int s = 0; s < 4; s++) { m[s] = -1.0e30f; lv[s] = 0.f; }

    int rbid0 = (row0 + mb) >> 4;   // mf adds +1

    for (int t = 0; t < NT; t++) {
        int b = t & 1;
        __syncthreads();           // everyone done reading buf b^1 (tile t-1)
        if (t + 1 < NT) {
            int blk = half * 32 + t + 1;
            const uint4* sBh = g_fhi_sw + blk * 2048;
            const uint4* sBl = g_flo_sw + blk * 2048;
            uint32_t dh = base + SM_BB(b ^ 1, 0);
            uint32_t dl = base + SM_BB(b ^ 1, 1);
#pragma unroll
            for (int i = 0; i < 4; i++) {
                int ch = tid * 4 + i;
                cp16(dh + ch * 16, sBh + ch);
                cp16(dl + ch * 16, sBl + ch);
            }
            CP_COMMIT();
            CP_WAIT1();
        } else {
            CP_WAIT0();
        }
        __syncthreads();           // tile t data visible CTA-wide

        float acc[2][4][4];
#pragma unroll
        for (int mf = 0; mf < 2; mf++)
#pragma unroll
            for (int nf = 0; nf < 4; nf++)
#pragma unroll
                for (int r = 0; r < 4; r++) acc[mf][nf][r] = 0.f;

        uint32_t bHi = base + SM_BB(b, 0) + (nb + rowB) * 256;
        uint32_t bLo = base + SM_BB(b, 1) + (nb + rowB) * 256;

#pragma unroll
        for (int s = 0; s < 8; s++) {
            uint32_t offA = (uint32_t)(((2 * s + cA) ^ xA) << 4);
            uint32_t offB = (uint32_t)(((2 * s + cB) ^ xB) << 4);
            uint32_t ah[8], al[8], bh[8], bl[8];
            LDSM4(&ah[0], aHi + offA);
            LDSM4(&ah[4], aHi + 4096 + offA);
            LDSM4(&al[0], aLo + offA);
            LDSM4(&al[4], aLo + 4096 + offA);
            LDSM4(&bh[0], bHi + offB);
            LDSM4(&bh[4], bHi + 4096 + offB);
            LDSM4(&bl[0], bLo + offB);
            LDSM4(&bl[4], bLo + 4096 + offB);
#pragma unroll
            for (int mf = 0; mf < 2; mf++)
#pragma unroll
                for (int nf = 0; nf < 4; nf++) {
                    MMA(acc[mf][nf], &ah[4 * mf], bh[2 * nf], bh[2 * nf + 1]);
                    MMA(acc[mf][nf], &ah[4 * mf], bl[2 * nf], bl[2 * nf + 1]);
                    MMA(acc[mf][nf], &al[4 * mf], bh[2 * nf], bh[2 * nf + 1]);
                }
        }

        // ---- epilogue: masked online max / sumexp ----
        int cbb[4];
#pragma unroll
        for (int nf = 0; nf < 4; nf++)
            cbb[nf] = (colbase + t * 128 + nb + nf * 8) >> 4;

#pragma unroll
        for (int mf = 0; mf < 2; mf++) {
            int rbid = rbid0 + mf;
#pragma unroll
            for (int h = 0; h < 2; h++) {
                int slot = mf * 2 + h;
                float v[8];
                float vmax = -3.0e38f;
#pragma unroll
                for (int nf = 0; nf < 4; nf++) {
                    bool msk = (rbid == cbb[nf]);
                    float x0 = msk ? -3.0e38f : acc[mf][nf][2 * h];
                    float x1 = msk ? -3.0e38f : acc[mf][nf][2 * h + 1];
                    v[2 * nf] = x0; v[2 * nf + 1] = x1;
                    vmax = fmaxf(vmax, fmaxf(x0, x1));
                }
                vmax = fmaxf(vmax, __shfl_xor_sync(0xffffffffu, vmax, 1));
                vmax = fmaxf(vmax, __shfl_xor_sync(0xffffffffu, vmax, 2));
                float newM = fmaxf(m[slot], vmax);
                float s = 0.f;
                if (vmax > newM - 6.2f) {
#pragma unroll
                    for (int j = 0; j < 8; j++) {
                        if (v[j] > newM - 6.2f)
                            s += __expf((v[j] - newM) * INV_T);
                    }
                }
                s += __shfl_xor_sync(0xffffffffu, s, 1);
                s += __shfl_xor_sync(0xffffffffu, s, 2);
                if (newM > m[slot]) {
                    lv[slot] = lv[slot] * __expf((m[slot] - newM) * INV_T) + s;
                    m[slot] = newM;
                } else {
                    lv[slot] += s;
                }
            }
        }
    }

    // ---- cross-warp combine (reuse A region) ----
    __syncthreads();
    float2* red = (float2*)cbase_ptr;   // [128 rows][4 wx]
    if ((l & 3) == 0) {
        int g = l >> 2;
#pragma unroll
        for (int mf = 0; mf < 2; mf++)
#pragma unroll
            for (int h = 0; h < 2; h++) {
                int slot = mf * 2 + h;
                int row_local = mb + mf * 16 + 8 * h + g;
                red[row_local * 4 + wx] = make_float2(m[slot], lv[slot]);
            }
    }
    __syncthreads();
    if (tid < 128) {
        float2 p0 = red[tid * 4 + 0], p1 = red[tid * 4 + 1];
        float2 p2 = red[tid * 4 + 2], p3 = red[tid * 4 + 3];
        float M = fmaxf(fmaxf(p0.x, p1.x), fmaxf(p2.x, p3.x));
        float L = p0.y * __expf((p0.x - M) * INV_T)
                + p1.y * __expf((p1.x - M) * INV_T)
                + p2.y * __expf((p2.x - M) * INV_T)
                + p3.y * __expf((p3.x - M) * INV_T);
        g_mp[half * N_ROWS + row0 + tid] = M;
        g_lp[half * N_ROWS + row0 + tid] = L;
    }
}

// ---------------- kernel 4: per-row class-loss terms (one warp per row) ----------------
__global__ void finish_kernel(const float* __restrict__ f,
                              const int* __restrict__ labels) {
    int i = (blockIdx.x * blockDim.x + threadIdx.x) >> 5;
    int lane = threadIdx.x & 31;
    int b = i >> 4;
    int lab = labels[b];
    float4 fv = ((const float4*)f)[i * 32 + lane];
    float4 Fv = ((const float4*)g_F)[lab * 32 + lane];
    float4 Bv = ((const float4*)g_Bb)[b * 32 + lane];
    float d = fv.x * (Fv.x - Bv.x) + fv.y * (Fv.y - Bv.y)
            + fv.z * (Fv.z - Bv.z) + fv.w * (Fv.w - Bv.w);
#pragma unroll
    for (int sh = 16; sh > 0; sh >>= 1)
        d += __shfl_xor_sync(0xffffffffu, d, sh);

    __shared__ float wterm[8];
    if (lane == 0) {
        float m0 = g_mp[i], m1 = g_mp[N_ROWS + i];
        float l0 = g_lp[i], l1 = g_lp[N_ROWS + i];
        float M = fmaxf(m0, m1);
        float L = l0 * __expf((m0 - M) * INV_T) + l1 * __expf((m1 - M) * INV_T);
        float lse = M * INV_T + logf(L);
        float P = (float)(g_cnt[lab] * 16 - 16);
        float term = (P > 0.f) ? -(d * INV_T - P * lse) / (P + 1e-8f) : 0.f;
        wterm[threadIdx.x >> 5] = term;
    }
    __syncthreads();
    if (threadIdx.x == 0) {
        float s = 0.f;
#pragma unroll
        for (int w = 0; w < 8; w++) s += wterm[w];
        atomicAdd(&g_class, (double)s);
    }
}

// ---------------- kernel 5: final scalar ----------------
__global__ void final_kernel(float* __restrict__ out) {
    double loss_class = g_class / (double)N_ROWS;
    double s_noise_logits = g_noise * (double)INV_T;
    double loss_noise = -(s_noise_logits / ((double)N_ROWS * 7.0)) / 0.07;
    double a = 1.0 / 3.0;
    out[0] = (float)(a * loss_class + a * loss_noise);
}

// ---------------- launch ----------------
extern "C" void kernel_launch(void* const* d_in, const int* in_sizes, int n_in,
                              void* d_out, int out_size) {
    const float* f = (const float*)d_in[0];
    const int* labels = (const int*)d_in[1];
    float* out = (float*)d_out;

    const int smem_bytes = 196608 + 1024;
    cudaFuncSetAttribute(gram_kernel, cudaFuncAttributeMaxDynamicSharedMemorySize, smem_bytes);

    zero_kernel<<<1, 256>>>();
    prep_kernel<<<512, 256>>>(f);
    precompute_kernel<<<NBATCH, 128>>>(f, labels);
    gram_kernel<<<128, 512, smem_bytes>>>();
    finish_kernel<<<1024, 256>>>(f, labels);
    final_kernel<<<1, 1>>>(out);
}

// round 4
// speedup vs baseline: 5.0128x; 1.3975x over previous
#include <cuda_runtime.h>
#include <cuda_bf16.h>
#include <math.h>
#include <stdint.h>

#define N_ROWS 8192
#define FD 128
#define INV_T 14.2857142857142857f   // 1/0.07
#define NBATCH 512
#define NCLASS 16

// ---------------- device-global scratch ----------------
// pre-swizzled bf16 hi/lo, 16B chunks: [block(64)][r(128)][chunk(16)]
__device__ uint4  g_fhi_sw[N_ROWS * 16];
__device__ uint4  g_flo_sw[N_ROWS * 16];
__device__ float  g_F[NCLASS * FD];
__device__ int    g_cnt[NCLASS];
__device__ float  g_Bb[NBATCH * FD];
__device__ float2 g_slot[N_ROWS * 64];   // per-(row, 128-block) LSE partials (m, l)
__device__ double g_noise;
__device__ double g_class;

// ---------------- helpers ----------------
__device__ __forceinline__ uint32_t smem_u32(const void* p) {
    uint32_t a;
    asm("{ .reg .u64 t; cvta.to.shared.u64 t, %1; cvt.u32.u64 %0, t; }" : "=r"(a) : "l"(p));
    return a;
}
__device__ __forceinline__ void cp16(uint32_t s, const void* g) {
    asm volatile("cp.async.cg.shared.global [%0], [%1], 16;" :: "r"(s), "l"(g) : "memory");
}
#define CP_COMMIT() asm volatile("cp.async.commit_group;" ::: "memory")
#define CP_WAIT1()  asm volatile("cp.async.wait_group 1;" ::: "memory")
#define CP_WAIT0()  asm volatile("cp.async.wait_group 0;" ::: "memory")

#define LDSM4(R, addr) \
    asm volatile("ldmatrix.sync.aligned.m8n8.x4.shared.b16 {%0,%1,%2,%3}, [%4];" \
        : "=r"((R)[0]), "=r"((R)[1]), "=r"((R)[2]), "=r"((R)[3]) : "r"(addr))

#define MMA(C, A, B0, B1) \
    asm volatile("mma.sync.aligned.m16n8k16.row.col.f32.bf16.bf16.f32 " \
        "{%0,%1,%2,%3}, {%4,%5,%6,%7}, {%8,%9}, {%0,%1,%2,%3};" \
        : "+f"((C)[0]), "+f"((C)[1]), "+f"((C)[2]), "+f"((C)[3]) \
        : "r"((A)[0]), "r"((A)[1]), "r"((A)[2]), "r"((A)[3]), "r"(B0), "r"(B1))

__device__ __forceinline__ uint32_t pack_bf2(__nv_bfloat16 a, __nv_bfloat16 b) {
    __nv_bfloat162 t(a, b);
    return *reinterpret_cast<uint32_t*>(&t);
}

// ---------------- kernel 0a: zero accumulators ----------------
__global__ void zero_kernel() {
    int t = threadIdx.x;
    for (int i = t; i < NCLASS * FD; i += blockDim.x) g_F[i] = 0.f;
    if (t < NCLASS) g_cnt[t] = 0;
    if (t == 0) { g_noise = 0.0; g_class = 0.0; }
}

// ---------------- kernel 0b: init slot table ----------------
__global__ void zero_slots() {
    int i = blockIdx.x * blockDim.x + threadIdx.x;
    g_slot[i] = make_float2(-1.0e30f, 0.f);
}

// ---------------- kernel 1: fp32 -> swizzled bf16 hi/lo ----------------
__global__ void prep_kernel(const float* __restrict__ f) {
    int idx = blockIdx.x * 256 + threadIdx.x;   // 0..131071
    int row = idx >> 4;
    int c = idx & 15;
    float4 v0 = ((const float4*)f)[row * 32 + c * 2];
    float4 v1 = ((const float4*)f)[row * 32 + c * 2 + 1];
    float vs[8] = { v0.x, v0.y, v0.z, v0.w, v1.x, v1.y, v1.z, v1.w };
    uint32_t hi[4], lo[4];
#pragma unroll
    for (int k = 0; k < 4; k++) {
        float a = vs[2 * k], b = vs[2 * k + 1];
        __nv_bfloat16 ha = __float2bfloat16(a), hb = __float2bfloat16(b);
        __nv_bfloat16 la = __float2bfloat16(a - __bfloat162float(ha));
        __nv_bfloat16 lb = __float2bfloat16(b - __bfloat162float(hb));
        hi[k] = pack_bf2(ha, hb);
        lo[k] = pack_bf2(la, lb);
    }
    int dst = ((row >> 7) << 11) + ((row & 127) << 4) + (c ^ (row & 7));
    g_fhi_sw[dst] = make_uint4(hi[0], hi[1], hi[2], hi[3]);
    g_flo_sw[dst] = make_uint4(lo[0], lo[1], lo[2], lo[3]);
}

// ---------------- kernel 2: per-batch sums, class sums, noise closed form ----------------
__global__ void precompute_kernel(const float* __restrict__ f,
                                  const int* __restrict__ labels) {
    int b = blockIdx.x;
    int t = threadIdx.x;
    float s16 = 0.f, s8a = 0.f, s8b = 0.f, ssq = 0.f;
#pragma unroll
    for (int r = 0; r < 16; r++) {
        float v = f[(b * 16 + r) * FD + t];
        s16 += v;
        if (r < 8) s8a += v; else s8b += v;
        ssq += v * v;
    }
    g_Bb[b * FD + t] = s16;
    int lab = labels[b];
    atomicAdd(&g_F[lab * FD + t], s16);
    if (t == 0) atomicAdd(&g_cnt[lab], 1);
    float c = s8a * s8a + s8b * s8b - ssq;
#pragma unroll
    for (int sh = 16; sh > 0; sh >>= 1)
        c += __shfl_xor_sync(0xffffffffu, c, sh);
    __shared__ float red[4];
    if ((t & 31) == 0) red[t >> 5] = c;
    __syncthreads();
    if (t == 0) atomicAdd(&g_noise, (double)(red[0] + red[1] + red[2] + red[3]));
}

// ---------------- kernel 3: symmetric HMMA gram + two-sided LSE epilogue ----------------
// 148 CTAs over the 2080 upper-triangle 128x128 tiles. 512 threads = 16 warps (4x4).
#define SM_A_HI 0
#define SM_A_LO 32768
#define SM_B(buf, hl) (65536 + (buf) * 65536 + (hl) * 32768)
#define SM_COLRED 196608
#define SM_ROWRED 200704
#define SMEM_BYTES (204800 + 1024)

__global__ void __launch_bounds__(512, 1) gram_kernel() {
    extern __shared__ char smraw[];
    uint32_t su = smem_u32(smraw);
    uint32_t base = (su + 1023u) & ~1023u;

    int tid = threadIdx.x;
    int l = tid & 31;
    int wid = tid >> 5;
    int wx = wid & 3, wy = wid >> 2;
    int mb = wy * 32, nb = wx * 32;

    // ---- tile range (triangular flat index) ----
    int cta = blockIdx.x;
    int t0 = cta * 14 + (cta < 8 ? cta : 8);
    int cnt = 14 + (cta < 8 ? 1 : 0);
    int rb = 0, off = 0;
    while (t0 >= off + (64 - rb)) { off += 64 - rb; rb++; }
    int cb = rb + (t0 - off);
    int a_rb = rb;
    int c0run = cb;

    // ---- prologue: A(rb) + B(cb)->buf0 ----
#pragma unroll
    for (int k = 0; k < 4; k++) {
        int ch = tid * 4 + k;
        cp16(base + SM_A_HI + ch * 16, g_fhi_sw + rb * 2048 + ch);
        cp16(base + SM_A_LO + ch * 16, g_flo_sw + rb * 2048 + ch);
        cp16(base + SM_B(0, 0) + ch * 16, g_fhi_sw + cb * 2048 + ch);
        cp16(base + SM_B(0, 1) + ch * 16, g_flo_sw + cb * 2048 + ch);
    }
    CP_COMMIT();

    // ---- lane addressing (as R3) ----
    int rowA = l & 15;
    int cA = l >> 4;
    int xA = rowA & 7;
    int rowB = (l & 7) + ((l >> 4) << 3);
    int cB = (l >> 3) & 1;
    int xB = rowB & 7;
    uint32_t aHi = base + SM_A_HI + (mb + rowA) * 256;
    uint32_t aLo = base + SM_A_LO + (mb + rowA) * 256;

    float m[4], lv[4];
#pragma unroll
    for (int s = 0; s < 4; s++) { m[s] = -1.0e30f; lv[s] = 0.f; }

    for (int i = 0; i < cnt; i++) {
        int b = i & 1;
        bool has_next = (i + 1 < cnt);
        int rbn = rb, cbn = cb + 1;
        if (cb == 63) { rbn = rb + 1; cbn = rb + 1; }

        __syncthreads();   // prev-tile MMAs done: buf b^1 and red areas free

        if (a_rb != rb) {  // run boundary: reload A (rare)
#pragma unroll
            for (int k = 0; k < 4; k++) {
                int ch = tid * 4 + k;
                cp16(base + SM_A_HI + ch * 16, g_fhi_sw + rb * 2048 + ch);
                cp16(base + SM_A_LO + ch * 16, g_flo_sw + rb * 2048 + ch);
            }
            CP_COMMIT();
            CP_WAIT0();
            a_rb = rb;
        }
        if (has_next) {
            uint32_t dh = base + SM_B(b ^ 1, 0);
            uint32_t dl = base + SM_B(b ^ 1, 1);
#pragma unroll
            for (int k = 0; k < 4; k++) {
                int ch = tid * 4 + k;
                cp16(dh + ch * 16, g_fhi_sw + cbn * 2048 + ch);
                cp16(dl + ch * 16, g_flo_sw + cbn * 2048 + ch);
            }
        }
        CP_COMMIT();
        CP_WAIT1();        // this tile's B complete
        __syncthreads();

        // ---- MMA: 3-pass hi/lo split ----
        float acc[2][4][4];
#pragma unroll
        for (int mf = 0; mf < 2; mf++)
#pragma unroll
            for (int nf = 0; nf < 4; nf++)
#pragma unroll
                for (int r = 0; r < 4; r++) acc[mf][nf][r] = 0.f;

        uint32_t bHi = base + SM_B(b, 0) + (nb + rowB) * 256;
        uint32_t bLo = base + SM_B(b, 1) + (nb + rowB) * 256;

#pragma unroll
        for (int s = 0; s < 8; s++) {
            uint32_t offA = (uint32_t)(((2 * s + cA) ^ xA) << 4);
            uint32_t offB = (uint32_t)(((2 * s + cB) ^ xB) << 4);
            uint32_t ah[8], al[8], bh[8], bl[8];
            LDSM4(&ah[0], aHi + offA);
            LDSM4(&ah[4], aHi + 4096 + offA);
            LDSM4(&al[0], aLo + offA);
            LDSM4(&al[4], aLo + 4096 + offA);
            LDSM4(&bh[0], bHi + offB);
            LDSM4(&bh[4], bHi + 4096 + offB);
            LDSM4(&bl[0], bLo + offB);
            LDSM4(&bl[4], bLo + 4096 + offB);
#pragma unroll
            for (int mf = 0; mf < 2; mf++)
#pragma unroll
                for (int nf = 0; nf < 4; nf++) {
                    MMA(acc[mf][nf], &ah[4 * mf], bh[2 * nf], bh[2 * nf + 1]);
                    MMA(acc[mf][nf], &ah[4 * mf], bl[2 * nf], bl[2 * nf + 1]);
                    MMA(acc[mf][nf], &al[4 * mf], bh[2 * nf], bh[2 * nf + 1]);
                }
        }

        // ---- row-side online epilogue (mask only fires when rb==cb) ----
        int cbb[4];
#pragma unroll
        for (int nf = 0; nf < 4; nf++)
            cbb[nf] = (cb * 128 + nb + nf * 8) >> 4;
        int rbid0 = (rb * 128 + mb) >> 4;

#pragma unroll
        for (int mf = 0; mf < 2; mf++) {
            int rbid = rbid0 + mf;
#pragma unroll
            for (int h = 0; h < 2; h++) {
                int slot = mf * 2 + h;
                float v[8];
                float vmax = -3.0e38f;
#pragma unroll
                for (int nf = 0; nf < 4; nf++) {
                    bool msk = (rbid == cbb[nf]);
                    float x0 = msk ? -3.0e38f : acc[mf][nf][2 * h];
                    float x1 = msk ? -3.0e38f : acc[mf][nf][2 * h + 1];
                    v[2 * nf] = x0; v[2 * nf + 1] = x1;
                    vmax = fmaxf(vmax, fmaxf(x0, x1));
                }
                vmax = fmaxf(vmax, __shfl_xor_sync(0xffffffffu, vmax, 1));
                vmax = fmaxf(vmax, __shfl_xor_sync(0xffffffffu, vmax, 2));
                float newM = fmaxf(m[slot], vmax);
                float s = 0.f;
                if (vmax > newM - 6.2f) {
#pragma unroll
                    for (int j = 0; j < 8; j++)
                        if (v[j] > newM - 6.2f)
                            s += __expf((v[j] - newM) * INV_T);
                }
                s += __shfl_xor_sync(0xffffffffu, s, 1);
                s += __shfl_xor_sync(0xffffffffu, s, 2);
                if (newM > m[slot]) {
                    lv[slot] = lv[slot] * __expf((m[slot] - newM) * INV_T) + s;
                    m[slot] = newM;
                } else {
                    lv[slot] += s;
                }
            }
        }

        // ---- col-side epilogue (off-diagonal only; no masking possible) ----
        if (rb < cb) {
            float2* colred = (float2*)(smraw + (base - su) + SM_COLRED);
            float cm[8], cs[8];
#pragma unroll
            for (int nf = 0; nf < 4; nf++)
#pragma unroll
                for (int par = 0; par < 2; par++) {
                    int ix = nf * 2 + par;
                    float a0 = acc[0][nf][par],     a1 = acc[0][nf][2 + par];
                    float b0 = acc[1][nf][par],     b1 = acc[1][nf][2 + par];
                    float mx = fmaxf(fmaxf(a0, a1), fmaxf(b0, b1));
                    mx = fmaxf(mx, __shfl_xor_sync(0xffffffffu, mx, 4));
                    mx = fmaxf(mx, __shfl_xor_sync(0xffffffffu, mx, 8));
                    mx = fmaxf(mx, __shfl_xor_sync(0xffffffffu, mx, 16));
                    float s = 0.f;
                    if (a0 > mx - 6.2f) s += __expf((a0 - mx) * INV_T);
                    if (a1 > mx - 6.2f) s += __expf((a1 - mx) * INV_T);
                    if (b0 > mx - 6.2f) s += __expf((b0 - mx) * INV_T);
                    if (b1 > mx - 6.2f) s += __expf((b1 - mx) * INV_T);
                    s += __shfl_xor_sync(0xffffffffu, s, 4);
                    s += __shfl_xor_sync(0xffffffffu, s, 8);
                    s += __shfl_xor_sync(0xffffffffu, s, 16);
                    cm[ix] = mx; cs[ix] = s;
                }
            if (l < 4) {
#pragma unroll
                for (int nf = 0; nf < 4; nf++)
#pragma unroll
                    for (int par = 0; par < 2; par++)
                        colred[wy * 128 + nb + nf * 8 + 2 * l + par] =
                            make_float2(cm[nf * 2 + par], cs[nf * 2 + par]);
            }
            __syncthreads();
            if (tid < 128) {
                float2 p0 = colred[tid], p1 = colred[128 + tid];
                float2 p2 = colred[256 + tid], p3 = colred[384 + tid];
                float M = fmaxf(fmaxf(p0.x, p1.x), fmaxf(p2.x, p3.x));
                float L = p0.y * __expf((p0.x - M) * INV_T)
                        + p1.y * __expf((p1.x - M) * INV_T)
                        + p2.y * __expf((p2.x - M) * INV_T)
                        + p3.y * __expf((p3.x - M) * INV_T);
                g_slot[(cb * 128 + tid) * 64 + rb] = make_float2(M, L);
            }
        }

        // ---- row-side flush at run end ----
        bool runend = !has_next || (rbn != rb);
        if (runend) {
            float2* rowred = (float2*)(smraw + (base - su) + SM_ROWRED);
            __syncthreads();
            if ((l & 3) == 0) {
                int g = l >> 2;
#pragma unroll
                for (int mf = 0; mf < 2; mf++)
#pragma unroll
                    for (int h = 0; h < 2; h++) {
                        int slot = mf * 2 + h;
                        rowred[(mb + mf * 16 + 8 * h + g) * 4 + wx] =
                            make_float2(m[slot], lv[slot]);
                    }
            }
            __syncthreads();
            if (tid < 128) {
                float2 p0 = rowred[tid * 4 + 0], p1 = rowred[tid * 4 + 1];
                float2 p2 = rowred[tid * 4 + 2], p3 = rowred[tid * 4 + 3];
                float M = fmaxf(fmaxf(p0.x, p1.x), fmaxf(p2.x, p3.x));
                float L = p0.y * __expf((p0.x - M) * INV_T)
                        + p1.y * __expf((p1.x - M) * INV_T)
                        + p2.y * __expf((p2.x - M) * INV_T)
                        + p3.y * __expf((p3.x - M) * INV_T);
                g_slot[(rb * 128 + tid) * 64 + c0run] = make_float2(M, L);
            }
#pragma unroll
            for (int s = 0; s < 4; s++) { m[s] = -1.0e30f; lv[s] = 0.f; }
            c0run = cbn;
        }
        rb = rbn; cb = cbn;
    }
}

// ---------------- kernel 4: slot merge + per-row class-loss term (warp per row) ----------------
__global__ void finish_kernel(const float* __restrict__ f,
                              const int* __restrict__ labels) {
    int i = (blockIdx.x * blockDim.x + threadIdx.x) >> 5;
    int lane = threadIdx.x & 31;
    int b = i >> 4;
    int lab = labels[b];

    // merge 64 slots (2 per lane, then 5-level butterfly)
    float2 s0 = g_slot[i * 64 + 2 * lane];
    float2 s1 = g_slot[i * 64 + 2 * lane + 1];
    float M = fmaxf(s0.x, s1.x);
    float L = s0.y * __expf((s0.x - M) * INV_T) + s1.y * __expf((s1.x - M) * INV_T);
#pragma unroll
    for (int sh = 16; sh > 0; sh >>= 1) {
        float Mo = __shfl_xor_sync(0xffffffffu, M, sh);
        float Lo = __shfl_xor_sync(0xffffffffu, L, sh);
        float Mn = fmaxf(M, Mo);
        L = L * __expf((M - Mn) * INV_T) + Lo * __expf((Mo - Mn) * INV_T);
        M = Mn;
    }

    // closed-form positive sum
    float4 fv = ((const float4*)f)[i * 32 + lane];
    float4 Fv = ((const float4*)g_F)[lab * 32 + lane];
    float4 Bv = ((const float4*)g_Bb)[b * 32 + lane];
    float d = fv.x * (Fv.x - Bv.x) + fv.y * (Fv.y - Bv.y)
            + fv.z * (Fv.z - Bv.z) + fv.w * (Fv.w - Bv.w);
#pragma unroll
    for (int sh = 16; sh > 0; sh >>= 1)
        d += __shfl_xor_sync(0xffffffffu, d, sh);

    __shared__ float wterm[8];
    if (lane == 0) {
        float lse = M * INV_T + logf(L);
        float P = (float)(g_cnt[lab] * 16 - 16);
        float term = (P > 0.f) ? -(d * INV_T - P * lse) / (P + 1e-8f) : 0.f;
        wterm[threadIdx.x >> 5] = term;
    }
    __syncthreads();
    if (threadIdx.x == 0) {
        float s = 0.f;
#pragma unroll
        for (int w = 0; w < 8; w++) s += wterm[w];
        atomicAdd(&g_class, (double)s);
    }
}

// ---------------- kernel 5: final scalar ----------------
__global__ void final_kernel(float* __restrict__ out) {
    double loss_class = g_class / (double)N_ROWS;
    double s_noise_logits = g_noise * (double)INV_T;
    double loss_noise = -(s_noise_logits / ((double)N_ROWS * 7.0)) / 0.07;
    double a = 1.0 / 3.0;
    out[0] = (float)(a * loss_class + a * loss_noise);
}

// ---------------- launch ----------------
extern "C" void kernel_launch(void* const* d_in, const int* in_sizes, int n_in,
                              void* d_out, int out_size) {
    const float* f = (const float*)d_in[0];
    const int* labels = (const int*)d_in[1];
    float* out = (float*)d_out;

    cudaFuncSetAttribute(gram_kernel, cudaFuncAttributeMaxDynamicSharedMemorySize, SMEM_BYTES);

    zero_kernel<<<1, 256>>>();
    zero_slots<<<2048, 256>>>();
    prep_kernel<<<512, 256>>>(f);
    precompute_kernel<<<NBATCH, 128>>>(f, labels);
    gram_kernel<<<148, 512, SMEM_BYTES>>>();
    finish_kernel<<<1024, 256>>>(f, labels);
    final_kernel<<<1, 1>>>(out);
}